// round 13
// baseline (speedup 1.0000x reference)
#include <cuda_runtime.h>
#include <cuda_fp16.h>
#include <cstdint>
#include <math.h>

// Problem constants (fixed by the reference setup_inputs)
#define MPTS   4096
#define NBATCH 4
#define NITERS 50
#define NSLOTS 2            // batches concurrent per launch (L2-resident: 64MB)
#define GB     148          // blocks per slot -> 296 total = 2/SM on 148 SMs
#define GRID   (NSLOTS*GB)
#define NT     256
#define CR     8            // rows per full chunk
#define NFULL  3            // full chunks per block (27|28 rows -> 3 full + tail)
#define TPAD   152          // partial rows padded to 8*19 (pads stay zero)
#define INV_N  (1.0f/4096.0f)
#define USCALE 16777216.0f  // 2^24 : u scaled into half-friendly range
#define VSCALE 4096.0f      // INV_N * 2^24 : folded into colfix division
#define SURV_THRESH 1e-5f
#define NBARS  (2 + 2*NITERS)   // grid barriers per slot per launch

// Scratch (device globals; allocation-free per harness rules).
__device__ __half g_K16[NSLOTS][(size_t)MPTS * MPTS];   // 2 x 32 MB, L2-resident
__device__ float  g_u[NSLOTS][MPTS];
__device__ float  g_v[NSLOTS][MPTS];
__device__ float  g_T[NSLOTS][TPAD][MPTS];              // partials; rows 148..151 = 0
__device__ float  g_cmax[NSLOTS][GB];
__device__ float  g_loss[NBATCH][GB][3];                // cnt, velsq, bce
struct Bar { unsigned c; unsigned pad[31]; };           // 128B separation
__device__ Bar g_bar[NSLOTS];

__device__ __forceinline__ float warpMax(float v){
    #pragma unroll
    for (int o = 16; o; o >>= 1) v = fmaxf(v, __shfl_xor_sync(0xffffffffu, v, o));
    return v;
}
__device__ __forceinline__ float warpSum(float v){
    #pragma unroll
    for (int o = 16; o; o >>= 1) v += __shfl_xor_sync(0xffffffffu, v, o);
    return v;
}
__device__ __forceinline__ float ex2(float x){
    float r; asm("ex2.approx.f32 %0, %1;" : "=f"(r) : "f"(x)); return r;
}
__device__ __forceinline__ void pref(const void* p){
    asm volatile("prefetch.global.L1 [%0];" :: "l"(p));
}

// Software grid barrier among the GB blocks of one slot.
__device__ __forceinline__ void gbar(int slot, unsigned &tgt){
    __syncthreads();
    if (threadIdx.x == 0){
        __threadfence();
        atomicAdd(&g_bar[slot].c, 1u);
        while (*((volatile unsigned*)&g_bar[slot].c) < tgt) __nanosleep(32);
    }
    __syncthreads();
    tgt += GB;
}

// Convert two uint4s (16 halfs) of a K row to float (final phase only).
__device__ __forceinline__ void cvt16(const uint4 &a, const uint4 &b, float *kf){
    const __half2* ha = (const __half2*)&a;
    const __half2* hb = (const __half2*)&b;
    #pragma unroll
    for (int q = 0; q < 4; q++){
        float2 f = __half22float2(ha[q]); kf[2*q]   = f.x; kf[2*q+1]   = f.y;
        float2 g = __half22float2(hb[q]); kf[8+2*q] = g.x; kf[8+2*q+1] = g.y;
    }
}

// ---------------------------------------------------------------------------
// Persistent kernel: 2 batch slots of 148 blocks each (one block of each slot
// per SM). Phases per slot: cmax -> exp(K16) -> 50x(rowpass -> colfix) ->
// argmax/loss partials. Rowpass: HFMA2, unconditional 8-row chunks; ONE
// __syncthreads per chunk (every warp redundantly reduces all 8 rows after
// the sync -> no second sync; identical summation order -> bitwise-same
// result). K chunk 0/1 of the next iteration is prefetched into L1 before
// each grid barrier so the barrier wait overlaps L2 latency.
// ---------------------------------------------------------------------------
__global__ void __launch_bounds__(NT, 2) k_persist(
        const float* __restrict__ x0p, const float* __restrict__ xgp,
        const float* __restrict__ vpp, const float* __restrict__ alp,
        int b0, unsigned base)
{
    int t = threadIdx.x, warp = t >> 5, lane = t & 31;
    int slot = (blockIdx.x >= GB) ? 1 : 0;
    int blk  = blockIdx.x - slot * GB;
    const float* x0 = x0p + (size_t)slot * MPTS * 3;
    const float* xg = xgp + (size_t)slot * MPTS * 3;
    const float* vp = vpp + (size_t)slot * MPTS * 3;
    const float* al = alp + (size_t)slot * MPTS;
    __half* Kh = g_K16[slot];

    __shared__ float red[2][CR][NT];        // row-sum partials (parity buffered)
    __shared__ float sr8[8];
    __shared__ float s_scalar;
    __shared__ float smx[8];
    __shared__ int   smi[8];
    __shared__ float sB[8][33];             // colfix transpose buffer

    unsigned tgt = base + GB;
    int rstart = (blk * MPTS) / GB;
    int rend   = ((blk + 1) * MPTS) / GB;   // 27 or 28 rows
    int ncols  = rend - rstart;

    // Thread t owns columns j = 8t..8t+7 and 2048+8t..2048+8t+7.
    {
        float gx[16], gy[16], gz[16];
        #pragma unroll
        for (int h = 0; h < 2; h++){
            const float* bg = xg + (size_t)h * 2048 * 3 + 24 * t;
            #pragma unroll
            for (int c = 0; c < 8; c++){
                gx[8*h+c] = bg[3*c]; gy[8*h+c] = bg[3*c+1]; gz[8*h+c] = bg[3*c+2];
            }
        }

        // ---- Phase 0: block-local cost max -------------------------------
        float mx = 0.f;
        for (int i = rstart; i < rend; i++){
            float ax = x0[3*i], ay = x0[3*i+1], az = x0[3*i+2];
            #pragma unroll
            for (int c = 0; c < 16; c++){
                float dx = ax-gx[c], dy = ay-gy[c], dz = az-gz[c];
                mx = fmaxf(mx, dx*dx + dy*dy + dz*dz);
            }
        }
        mx = warpMax(mx);
        if (lane == 0) sr8[warp] = mx;
        __syncthreads();
        if (t == 0){
            float m = sr8[0];
            #pragma unroll
            for (int w = 1; w < 8; w++) m = fmaxf(m, sr8[w]);
            g_cmax[slot][blk] = m;
        }
        gbar(slot, tgt);

        // ---- Phase 1: global max -> scale; K16 = 2^4*exp(-C/(reg*cmax)) --
        float mc = (t < GB) ? __ldcg(&g_cmax[slot][t]) : 0.f;
        mc = warpMax(mc);
        if (lane == 0) sr8[warp] = mc;
        __syncthreads();
        if (t == 0){
            float m = sr8[0];
            #pragma unroll
            for (int w = 1; w < 8; w++) m = fmaxf(m, sr8[w]);
            s_scalar = -1.44269504088896340736f / (0.1f * m);
        }
        __syncthreads();
        float scale = s_scalar;
        for (int i = rstart; i < rend; i++){
            float ax = x0[3*i], ay = x0[3*i+1], az = x0[3*i+2];
            __half2 hk[8];
            #pragma unroll
            for (int c = 0; c < 16; c += 2){
                float dx = ax-gx[c],   dy = ay-gy[c],   dz = az-gz[c];
                float e0 = ex2(fmaf(dx*dx + dy*dy + dz*dz, scale, 4.0f));
                dx = ax-gx[c+1]; dy = ay-gy[c+1]; dz = az-gz[c+1];
                float e1 = ex2(fmaf(dx*dx + dy*dy + dz*dz, scale, 4.0f));
                hk[c/2] = __floats2half2_rn(e0, e1);
            }
            uint4* Krow = (uint4*)(Kh + (size_t)i * MPTS);
            Krow[t]       = *(uint4*)&hk[0];
            Krow[256 + t] = *(uint4*)&hk[4];
        }
        if (blk == 0){
            #pragma unroll
            for (int q = 0; q < 16; q++) g_v[slot][t + 256*q] = 1.0f;
        }
    }
    gbar(slot, tgt);

    // ---- Phase 2: 50 Sinkhorn iterations (HFMA2 inner loops) -------------
    for (int it = 0; it < NITERS; it++){
        // load v (cross-block -> L2) and convert to half2 lanes
        __half2 vh[8];
        {
            float4 v0 = __ldcg((const float4*)(g_v[slot] + 8*t));
            float4 v1 = __ldcg((const float4*)(g_v[slot] + 8*t + 4));
            float4 v2 = __ldcg((const float4*)(g_v[slot] + 2048 + 8*t));
            float4 v3 = __ldcg((const float4*)(g_v[slot] + 2048 + 8*t + 4));
            vh[0] = __floats2half2_rn(v0.x, v0.y); vh[1] = __floats2half2_rn(v0.z, v0.w);
            vh[2] = __floats2half2_rn(v1.x, v1.y); vh[3] = __floats2half2_rn(v1.z, v1.w);
            vh[4] = __floats2half2_rn(v2.x, v2.y); vh[5] = __floats2half2_rn(v2.z, v2.w);
            vh[6] = __floats2half2_rn(v3.x, v3.y); vh[7] = __floats2half2_rn(v3.z, v3.w);
        }
        float Tacc[16];
        #pragma unroll
        for (int c = 0; c < 16; c++) Tacc[c] = 0.f;

        const __half2 hz = __floats2half2_rn(0.f, 0.f);

        // ---- 3 full chunks of 8 rows: ONE sync per chunk
        #pragma unroll 1
        for (int f = 0; f < NFULL; f++){
            int ib = rstart + f * CR;
            int par = f & 1;
            // Pass A: 8 independent row sums in half2, no predicates, no syncs
            #pragma unroll
            for (int r = 0; r < CR; r++){
                const uint4* Kr = (const uint4*)(Kh + (size_t)(ib + r) * MPTS);
                uint4 ka = Kr[t], kb = Kr[256 + t];
                const __half2* a2 = (const __half2*)&ka;
                const __half2* b2 = (const __half2*)&kb;
                __half2 acc = hz;
                #pragma unroll
                for (int q = 0; q < 4; q++) acc = __hfma2(a2[q], vh[q],   acc);
                #pragma unroll
                for (int q = 0; q < 4; q++) acc = __hfma2(b2[q], vh[4+q], acc);
                float2 fv = __half22float2(acc);
                red[par][r][t] = fv.x + fv.y;
            }
            __syncthreads();
            // Redundant reduce: EVERY warp reduces all 8 rows (same order as
            // before -> bitwise-identical u); u' kept in registers, no 2nd sync.
            __half2 uh[CR];
            #pragma unroll
            for (int r = 0; r < CR; r++){
                float S = 0.f;
                #pragma unroll
                for (int q = 0; q < 8; q++) S += red[par][r][lane + 32*q];
                S = warpSum(S);
                float u = INV_N / S;
                if (t == 0) g_u[slot][ib + r] = u;
                uh[r] = __float2half2_rn(u * USCALE);
            }
            // Pass B: re-read same rows (L1-hot); chunk subtotal in half2
            {
                __half2 Tsub[8];
                #pragma unroll
                for (int q = 0; q < 8; q++) Tsub[q] = hz;
                #pragma unroll
                for (int r = 0; r < CR; r++){
                    const uint4* Kr = (const uint4*)(Kh + (size_t)(ib + r) * MPTS);
                    uint4 ka = Kr[t], kb = Kr[256 + t];
                    const __half2* a2 = (const __half2*)&ka;
                    const __half2* b2 = (const __half2*)&kb;
                    #pragma unroll
                    for (int q = 0; q < 4; q++){
                        Tsub[q]   = __hfma2(a2[q], uh[r], Tsub[q]);
                        Tsub[4+q] = __hfma2(b2[q], uh[r], Tsub[4+q]);
                    }
                }
                #pragma unroll
                for (int q = 0; q < 8; q++){
                    float2 fv = __half22float2(Tsub[q]);
                    Tacc[2*q]   += fv.x;
                    Tacc[2*q+1] += fv.y;
                }
            }
        }

        // ---- tail chunk: nr = 3 or 4 rows, predicated
        {
            int ib = rstart + NFULL * CR;
            int nr = rend - ib;
            int par = NFULL & 1;
            #pragma unroll
            for (int r = 0; r < 4; r++){
                if (r < nr){
                    const uint4* Kr = (const uint4*)(Kh + (size_t)(ib + r) * MPTS);
                    uint4 ka = Kr[t], kb = Kr[256 + t];
                    const __half2* a2 = (const __half2*)&ka;
                    const __half2* b2 = (const __half2*)&kb;
                    __half2 acc = hz;
                    #pragma unroll
                    for (int q = 0; q < 4; q++) acc = __hfma2(a2[q], vh[q],   acc);
                    #pragma unroll
                    for (int q = 0; q < 4; q++) acc = __hfma2(b2[q], vh[4+q], acc);
                    float2 fv = __half22float2(acc);
                    red[par][r][t] = fv.x + fv.y;
                }
            }
            __syncthreads();
            __half2 uh[4];
            #pragma unroll
            for (int r = 0; r < 4; r++){
                float S = 1.f;
                if (r < nr){
                    S = 0.f;
                    #pragma unroll
                    for (int q = 0; q < 8; q++) S += red[par][r][lane + 32*q];
                    S = warpSum(S);
                }
                float u = INV_N / S;
                if (t == 0 && r < nr) g_u[slot][ib + r] = u;
                uh[r] = __float2half2_rn(u * USCALE);
            }
            {
                __half2 Tsub[8];
                #pragma unroll
                for (int q = 0; q < 8; q++) Tsub[q] = hz;
                #pragma unroll
                for (int r = 0; r < 4; r++){
                    if (r < nr){
                        const uint4* Kr = (const uint4*)(Kh + (size_t)(ib + r) * MPTS);
                        uint4 ka = Kr[t], kb = Kr[256 + t];
                        const __half2* a2 = (const __half2*)&ka;
                        const __half2* b2 = (const __half2*)&kb;
                        #pragma unroll
                        for (int q = 0; q < 4; q++){
                            Tsub[q]   = __hfma2(a2[q], uh[r], Tsub[q]);
                            Tsub[4+q] = __hfma2(b2[q], uh[r], Tsub[4+q]);
                        }
                    }
                }
                #pragma unroll
                for (int q = 0; q < 8; q++){
                    float2 fv = __half22float2(Tsub[q]);
                    Tacc[2*q]   += fv.x;
                    Tacc[2*q+1] += fv.y;
                }
            }
        }

        // store column partials (fp32, scaled by 2^24 via u')
        float4* Tp = (float4*)&g_T[slot][blk][0];
        Tp[2*t]       = make_float4(Tacc[0],  Tacc[1],  Tacc[2],  Tacc[3]);
        Tp[2*t+1]     = make_float4(Tacc[4],  Tacc[5],  Tacc[6],  Tacc[7]);
        Tp[512+2*t]   = make_float4(Tacc[8],  Tacc[9],  Tacc[10], Tacc[11]);
        Tp[512+2*t+1] = make_float4(Tacc[12], Tacc[13], Tacc[14], Tacc[15]);

        // Prefetch next iteration's chunk 0 into L1 (overlaps barrier wait;
        // K is read-only, so this is always safe).
        #pragma unroll
        for (int r = 0; r < CR; r++){
            const char* src = (const char*)(Kh + (size_t)(rstart + r) * MPTS) + 16 * t;
            pref(src); pref(src + 4096);
        }
        gbar(slot, tgt);

        // Column fix (coalesced): warp w sums partial rows [19w, 19w+19) at
        // column rstart+lane, then an 8-way SMEM combine. Pads are zero.
        {
            float s = 0.f;
            if (lane < ncols){
                int c = rstart + lane;
                #pragma unroll
                for (int p = 0; p < 19; p++)
                    s += __ldcg(&g_T[slot][19*warp + p][c]);
            }
            sB[warp][lane] = s;
            __syncthreads();
            if (t < 32 && lane < ncols){
                float T = 0.f;
                #pragma unroll
                for (int g = 0; g < 8; g++) T += sB[g][lane];
                g_v[slot][rstart + lane] = VSCALE / T;
            }
        }
        // Prefetch next iteration's chunk 1 into L1 (overlaps barrier wait).
        #pragma unroll
        for (int r = 0; r < CR; r++){
            const char* src = (const char*)(Kh + (size_t)(rstart + CR + r) * MPTS) + 16 * t;
            pref(src); pref(src + 4096);
        }
        gbar(slot, tgt);
    }

    // ---- Phase 3: argmax of pi = u*K*v, survival, loss partials ----------
    {
        float vr[16];
        {
            float4 v0 = __ldcg((const float4*)(g_v[slot] + 8*t));
            float4 v1 = __ldcg((const float4*)(g_v[slot] + 8*t + 4));
            float4 v2 = __ldcg((const float4*)(g_v[slot] + 2048 + 8*t));
            float4 v3 = __ldcg((const float4*)(g_v[slot] + 2048 + 8*t + 4));
            vr[0]=v0.x; vr[1]=v0.y; vr[2]=v0.z;  vr[3]=v0.w;
            vr[4]=v1.x; vr[5]=v1.y; vr[6]=v1.z;  vr[7]=v1.w;
            vr[8]=v2.x; vr[9]=v2.y; vr[10]=v2.z; vr[11]=v2.w;
            vr[12]=v3.x; vr[13]=v3.y; vr[14]=v3.z; vr[15]=v3.w;
        }
        float cnt = 0.f, velsq = 0.f, bce = 0.f;   // thread 0 accumulates
        for (int i = rstart; i < rend; i++){
            const uint4* Kr = (const uint4*)(Kh + (size_t)i * MPTS);
            uint4 ka = Kr[t], kb = Kr[256 + t];
            float kf[16];
            cvt16(ka, kb, kf);
            float m = -1.f; int mi = 0;
            #pragma unroll
            for (int c = 0; c < 16; c++){
                float p = kf[c] * vr[c];
                int j = (c < 8) ? (8*t + c) : (2048 + 8*t + c - 8);
                if (p > m){ m = p; mi = j; }
            }
            #pragma unroll
            for (int o = 16; o; o >>= 1){
                float om = __shfl_xor_sync(0xffffffffu, m, o);
                int   oi = __shfl_xor_sync(0xffffffffu, mi, o);
                if (om > m || (om == m && oi < mi)){ m = om; mi = oi; }
            }
            if (lane == 0){ smx[warp] = m; smi[warp] = mi; }
            __syncthreads();
            if (t == 0){
                #pragma unroll
                for (int w = 1; w < 8; w++){
                    if (smx[w] > m || (smx[w] == m && smi[w] < mi)){
                        m = smx[w]; mi = smi[w];
                    }
                }
                float p = g_u[slot][i] * m;
                float a_i = al[i];
                float sp = fmaxf(a_i, 0.f) + log1pf(expf(-fabsf(a_i)));
                bce += sp;
                if (p > SURV_THRESH){
                    cnt += 1.f;
                    bce -= a_i;
                    #pragma unroll
                    for (int d = 0; d < 3; d++){
                        float vt = xg[3*mi + d] - x0[3*i + d];
                        float df = vp[3*i + d] - vt;
                        velsq = fmaf(df, df, velsq);
                    }
                }
            }
            __syncthreads();
        }
        if (t == 0){
            g_loss[b0 + slot][blk][0] = cnt;
            g_loss[b0 + slot][blk][1] = velsq;
            g_loss[b0 + slot][blk][2] = bce;
        }
    }
}

// ---------------------------------------------------------------------------
// Final reduction; also resets the barrier counters for the next replay
// (counters start at 0 from static init; every kernel_launch ends here).
__global__ void __launch_bounds__(NT) k_loss(float* __restrict__ out){
    int t = threadIdx.x;
    if (t < NSLOTS) g_bar[t].c = 0u;
    float cnt = 0.f, velsq = 0.f, bce = 0.f;
    for (int idx = t; idx < NBATCH * GB; idx += NT){
        int b = idx / GB, p = idx % GB;
        cnt   += g_loss[b][p][0];
        velsq += g_loss[b][p][1];
        bce   += g_loss[b][p][2];
    }
    cnt = warpSum(cnt); velsq = warpSum(velsq); bce = warpSum(bce);
    __shared__ float sc[8], sv[8], sb2[8];
    if ((t & 31) == 0){ sc[t>>5] = cnt; sv[t>>5] = velsq; sb2[t>>5] = bce; }
    __syncthreads();
    if (t == 0){
        float C = 0.f, V = 0.f, Bc = 0.f;
        #pragma unroll
        for (int w = 0; w < 8; w++){ C += sc[w]; V += sv[w]; Bc += sb2[w]; }
        float denom = fmaxf(C, 1.f);
        out[0] = V / denom + Bc / (float)(NBATCH * MPTS);
    }
}

// ---------------------------------------------------------------------------
extern "C" void kernel_launch(void* const* d_in, const int* in_sizes, int n_in,
                              void* d_out, int out_size){
    const float* x0 = (const float*)d_in[0];   // (B, M, 3)
    const float* xg = (const float*)d_in[1];   // (B, K, 3)
    const float* vp = (const float*)d_in[2];   // (B, M, 3)
    const float* al = (const float*)d_in[3];   // (B, M, 1)
    (void)in_sizes; (void)n_in; (void)out_size;

    for (int l = 0; l < NBATCH / NSLOTS; l++){
        int b0 = l * NSLOTS;
        k_persist<<<GRID, NT>>>(x0 + (size_t)b0 * MPTS * 3,
                                xg + (size_t)b0 * MPTS * 3,
                                vp + (size_t)b0 * MPTS * 3,
                                al + (size_t)b0 * MPTS,
                                b0, (unsigned)(l * NBARS * GB));
    }
    k_loss<<<1, NT>>>((float*)d_out);
}

// round 14
// speedup vs baseline: 1.3775x; 1.3775x over previous
#include <cuda_runtime.h>
#include <cuda_fp16.h>
#include <cstdint>
#include <math.h>

// Problem constants (fixed by the reference setup_inputs)
#define MPTS   4096
#define NBATCH 4
#define NITERS 50
#define NSLOTS 2            // batches concurrent per launch (L2-resident: 64MB)
#define GB     148          // blocks per slot -> 296 total = 2/SM on 148 SMs
#define GRID   (NSLOTS*GB)
#define NT     256
#define CR     8            // rows per full chunk
#define CR3    12           // max rows in merged third chunk (11 or 12)
#define TPAD   152          // partial rows padded to 8*19 (pads stay zero)
#define INV_N  (1.0f/4096.0f)
#define USCALE 16777216.0f  // 2^24 : u scaled into half-friendly range
#define VSCALE 4096.0f      // INV_N * 2^24 : folded into colfix division
#define SURV_THRESH 1e-5f
#define NBARS  (2 + 2*NITERS)   // grid barriers per slot per launch

// Scratch (device globals; allocation-free per harness rules).
__device__ __half g_K16[NSLOTS][(size_t)MPTS * MPTS];   // 2 x 32 MB, L2-resident
__device__ float  g_u[NSLOTS][MPTS];
__device__ float  g_v[NSLOTS][MPTS];
__device__ float  g_T[NSLOTS][TPAD][MPTS];              // partials; rows 148..151 = 0
__device__ float  g_cmax[NSLOTS][GB];
__device__ float  g_loss[NBATCH][GB][3];                // cnt, velsq, bce
struct Bar { unsigned c; unsigned pad[31]; };           // 128B separation
__device__ Bar g_bar[NSLOTS];

__device__ __forceinline__ float warpMax(float v){
    #pragma unroll
    for (int o = 16; o; o >>= 1) v = fmaxf(v, __shfl_xor_sync(0xffffffffu, v, o));
    return v;
}
__device__ __forceinline__ float warpSum(float v){
    #pragma unroll
    for (int o = 16; o; o >>= 1) v += __shfl_xor_sync(0xffffffffu, v, o);
    return v;
}
__device__ __forceinline__ float ex2(float x){
    float r; asm("ex2.approx.f32 %0, %1;" : "=f"(r) : "f"(x)); return r;
}

// Software grid barrier among the GB blocks of one slot.
__device__ __forceinline__ void gbar(int slot, unsigned &tgt){
    __syncthreads();
    if (threadIdx.x == 0){
        __threadfence();
        atomicAdd(&g_bar[slot].c, 1u);
        while (*((volatile unsigned*)&g_bar[slot].c) < tgt) __nanosleep(32);
    }
    __syncthreads();
    tgt += GB;
}

// Convert two uint4s (16 halfs) of a K row to float (final phase only).
__device__ __forceinline__ void cvt16(const uint4 &a, const uint4 &b, float *kf){
    const __half2* ha = (const __half2*)&a;
    const __half2* hb = (const __half2*)&b;
    #pragma unroll
    for (int q = 0; q < 4; q++){
        float2 f = __half22float2(ha[q]); kf[2*q]   = f.x; kf[2*q+1]   = f.y;
        float2 g = __half22float2(hb[q]); kf[8+2*q] = g.x; kf[8+2*q+1] = g.y;
    }
}

// ---------------------------------------------------------------------------
// Persistent kernel: 2 batch slots of 148 blocks each (one block of each slot
// per SM). Phases per slot: cmax -> exp(K16) -> 50x(rowpass -> colfix) ->
// argmax/loss partials. Rowpass: HFMA2; chunks {8, 8, 11|12} (tail merged
// into chunk 3 -> 6 __syncthreads/iter instead of 8). Chunk <= 12 rows keeps
// 2 blocks x 96KB inside L1 so pass B re-reads stay L1-hot (the R8 lesson).
// Summation order and Tsub flush boundaries (rows 8,16,24) are unchanged ->
// bitwise-identical result to R12.
// ---------------------------------------------------------------------------
__global__ void __launch_bounds__(NT, 2) k_persist(
        const float* __restrict__ x0p, const float* __restrict__ xgp,
        const float* __restrict__ vpp, const float* __restrict__ alp,
        int b0, unsigned base)
{
    int t = threadIdx.x, warp = t >> 5, lane = t & 31;
    int slot = (blockIdx.x >= GB) ? 1 : 0;
    int blk  = blockIdx.x - slot * GB;
    const float* x0 = x0p + (size_t)slot * MPTS * 3;
    const float* xg = xgp + (size_t)slot * MPTS * 3;
    const float* vp = vpp + (size_t)slot * MPTS * 3;
    const float* al = alp + (size_t)slot * MPTS;
    __half* Kh = g_K16[slot];

    __shared__ float   red[CR3][NT];        // row-sum partials (12 KB)
    __shared__ __half2 su[CR3];             // scaled u' per chunk row
    __shared__ float   sr8[8];
    __shared__ float   s_scalar;
    __shared__ float   smx[8];
    __shared__ int     smi[8];
    __shared__ float   sB[8][33];           // colfix transpose buffer

    unsigned tgt = base + GB;
    int rstart = (blk * MPTS) / GB;
    int rend   = ((blk + 1) * MPTS) / GB;   // 27 or 28 rows
    int ncols  = rend - rstart;
    int ncr3   = ncols - 16;                // 11 or 12 rows in chunk 3

    // Thread t owns columns j = 8t..8t+7 and 2048+8t..2048+8t+7.
    {
        float gx[16], gy[16], gz[16];
        #pragma unroll
        for (int h = 0; h < 2; h++){
            const float* bg = xg + (size_t)h * 2048 * 3 + 24 * t;
            #pragma unroll
            for (int c = 0; c < 8; c++){
                gx[8*h+c] = bg[3*c]; gy[8*h+c] = bg[3*c+1]; gz[8*h+c] = bg[3*c+2];
            }
        }

        // ---- Phase 0: block-local cost max -------------------------------
        float mx = 0.f;
        for (int i = rstart; i < rend; i++){
            float ax = x0[3*i], ay = x0[3*i+1], az = x0[3*i+2];
            #pragma unroll
            for (int c = 0; c < 16; c++){
                float dx = ax-gx[c], dy = ay-gy[c], dz = az-gz[c];
                mx = fmaxf(mx, dx*dx + dy*dy + dz*dz);
            }
        }
        mx = warpMax(mx);
        if (lane == 0) sr8[warp] = mx;
        __syncthreads();
        if (t == 0){
            float m = sr8[0];
            #pragma unroll
            for (int w = 1; w < 8; w++) m = fmaxf(m, sr8[w]);
            g_cmax[slot][blk] = m;
        }
        gbar(slot, tgt);

        // ---- Phase 1: global max -> scale; K16 = 2^4*exp(-C/(reg*cmax)) --
        float mc = (t < GB) ? __ldcg(&g_cmax[slot][t]) : 0.f;
        mc = warpMax(mc);
        if (lane == 0) sr8[warp] = mc;
        __syncthreads();
        if (t == 0){
            float m = sr8[0];
            #pragma unroll
            for (int w = 1; w < 8; w++) m = fmaxf(m, sr8[w]);
            s_scalar = -1.44269504088896340736f / (0.1f * m);
        }
        __syncthreads();
        float scale = s_scalar;
        for (int i = rstart; i < rend; i++){
            float ax = x0[3*i], ay = x0[3*i+1], az = x0[3*i+2];
            __half2 hk[8];
            #pragma unroll
            for (int c = 0; c < 16; c += 2){
                float dx = ax-gx[c],   dy = ay-gy[c],   dz = az-gz[c];
                float e0 = ex2(fmaf(dx*dx + dy*dy + dz*dz, scale, 4.0f));
                dx = ax-gx[c+1]; dy = ay-gy[c+1]; dz = az-gz[c+1];
                float e1 = ex2(fmaf(dx*dx + dy*dy + dz*dz, scale, 4.0f));
                hk[c/2] = __floats2half2_rn(e0, e1);
            }
            uint4* Krow = (uint4*)(Kh + (size_t)i * MPTS);
            Krow[t]       = *(uint4*)&hk[0];
            Krow[256 + t] = *(uint4*)&hk[4];
        }
        if (blk == 0){
            #pragma unroll
            for (int q = 0; q < 16; q++) g_v[slot][t + 256*q] = 1.0f;
        }
    }
    gbar(slot, tgt);

    // ---- Phase 2: 50 Sinkhorn iterations (HFMA2 inner loops) -------------
    for (int it = 0; it < NITERS; it++){
        // load v (cross-block -> L2) and convert to half2 lanes
        __half2 vh[8];
        {
            float4 v0 = __ldcg((const float4*)(g_v[slot] + 8*t));
            float4 v1 = __ldcg((const float4*)(g_v[slot] + 8*t + 4));
            float4 v2 = __ldcg((const float4*)(g_v[slot] + 2048 + 8*t));
            float4 v3 = __ldcg((const float4*)(g_v[slot] + 2048 + 8*t + 4));
            vh[0] = __floats2half2_rn(v0.x, v0.y); vh[1] = __floats2half2_rn(v0.z, v0.w);
            vh[2] = __floats2half2_rn(v1.x, v1.y); vh[3] = __floats2half2_rn(v1.z, v1.w);
            vh[4] = __floats2half2_rn(v2.x, v2.y); vh[5] = __floats2half2_rn(v2.z, v2.w);
            vh[6] = __floats2half2_rn(v3.x, v3.y); vh[7] = __floats2half2_rn(v3.z, v3.w);
        }
        float Tacc[16];
        #pragma unroll
        for (int c = 0; c < 16; c++) Tacc[c] = 0.f;

        const __half2 hz = __floats2half2_rn(0.f, 0.f);

        // ---- Chunks 0 and 1: 8 unconditional rows each, 2 syncs/chunk
        #pragma unroll 1
        for (int f = 0; f < 2; f++){
            int ib = rstart + f * CR;
            // Pass A: 8 independent row sums in half2, no predicates, no syncs
            #pragma unroll
            for (int r = 0; r < CR; r++){
                const uint4* Kr = (const uint4*)(Kh + (size_t)(ib + r) * MPTS);
                uint4 ka = Kr[t], kb = Kr[256 + t];
                const __half2* a2 = (const __half2*)&ka;
                const __half2* b2 = (const __half2*)&kb;
                __half2 acc = hz;
                #pragma unroll
                for (int q = 0; q < 4; q++) acc = __hfma2(a2[q], vh[q],   acc);
                #pragma unroll
                for (int q = 0; q < 4; q++) acc = __hfma2(b2[q], vh[4+q], acc);
                float2 fv = __half22float2(acc);
                red[r][t] = fv.x + fv.y;
            }
            __syncthreads();
            // Block reduce: warp w reduces row w
            {
                float S = 0.f;
                #pragma unroll
                for (int q = 0; q < 8; q++) S += red[warp][lane + 32*q];
                S = warpSum(S);
                if (lane == 0){
                    float u = INV_N / S;
                    g_u[slot][ib + warp] = u;
                    su[warp] = __float2half2_rn(u * USCALE);
                }
            }
            __syncthreads();
            // Pass B: re-read same rows (L1-hot); chunk subtotal in half2
            {
                __half2 Tsub[8];
                #pragma unroll
                for (int q = 0; q < 8; q++) Tsub[q] = hz;
                #pragma unroll
                for (int r = 0; r < CR; r++){
                    const uint4* Kr = (const uint4*)(Kh + (size_t)(ib + r) * MPTS);
                    uint4 ka = Kr[t], kb = Kr[256 + t];
                    const __half2* a2 = (const __half2*)&ka;
                    const __half2* b2 = (const __half2*)&kb;
                    __half2 uh = su[r];
                    #pragma unroll
                    for (int q = 0; q < 4; q++){
                        Tsub[q]   = __hfma2(a2[q], uh, Tsub[q]);
                        Tsub[4+q] = __hfma2(b2[q], uh, Tsub[4+q]);
                    }
                }
                #pragma unroll
                for (int q = 0; q < 8; q++){
                    float2 fv = __half22float2(Tsub[q]);
                    Tacc[2*q]   += fv.x;
                    Tacc[2*q+1] += fv.y;
                }
            }
        }

        // ---- Chunk 2: 11|12 rows (8 + 3|4), 2 syncs total ----------------
        {
            int ib = rstart + 16;
            // Pass A: rows 0..7 unconditional, rows 8..11 predicated
            #pragma unroll
            for (int r = 0; r < 8; r++){
                const uint4* Kr = (const uint4*)(Kh + (size_t)(ib + r) * MPTS);
                uint4 ka = Kr[t], kb = Kr[256 + t];
                const __half2* a2 = (const __half2*)&ka;
                const __half2* b2 = (const __half2*)&kb;
                __half2 acc = hz;
                #pragma unroll
                for (int q = 0; q < 4; q++) acc = __hfma2(a2[q], vh[q],   acc);
                #pragma unroll
                for (int q = 0; q < 4; q++) acc = __hfma2(b2[q], vh[4+q], acc);
                float2 fv = __half22float2(acc);
                red[r][t] = fv.x + fv.y;
            }
            #pragma unroll
            for (int r = 8; r < CR3; r++){
                if (r < ncr3){
                    const uint4* Kr = (const uint4*)(Kh + (size_t)(ib + r) * MPTS);
                    uint4 ka = Kr[t], kb = Kr[256 + t];
                    const __half2* a2 = (const __half2*)&ka;
                    const __half2* b2 = (const __half2*)&kb;
                    __half2 acc = hz;
                    #pragma unroll
                    for (int q = 0; q < 4; q++) acc = __hfma2(a2[q], vh[q],   acc);
                    #pragma unroll
                    for (int q = 0; q < 4; q++) acc = __hfma2(b2[q], vh[4+q], acc);
                    float2 fv = __half22float2(acc);
                    red[r][t] = fv.x + fv.y;
                }
            }
            __syncthreads();
            // Block reduce: warp w reduces row w; warps 0..ncr3-9 also row 8+w
            {
                float S = 0.f;
                #pragma unroll
                for (int q = 0; q < 8; q++) S += red[warp][lane + 32*q];
                S = warpSum(S);
                if (lane == 0){
                    float u = INV_N / S;
                    g_u[slot][ib + warp] = u;
                    su[warp] = __float2half2_rn(u * USCALE);
                }
                if (warp < ncr3 - 8){
                    float S2 = 0.f;
                    #pragma unroll
                    for (int q = 0; q < 8; q++) S2 += red[8 + warp][lane + 32*q];
                    S2 = warpSum(S2);
                    if (lane == 0){
                        float u2 = INV_N / S2;
                        g_u[slot][ib + 8 + warp] = u2;
                        su[8 + warp] = __float2half2_rn(u2 * USCALE);
                    }
                }
            }
            __syncthreads();
            // Pass B group 1: rows 0..7 (flush boundary at row 24 preserved)
            {
                __half2 Tsub[8];
                #pragma unroll
                for (int q = 0; q < 8; q++) Tsub[q] = hz;
                #pragma unroll
                for (int r = 0; r < 8; r++){
                    const uint4* Kr = (const uint4*)(Kh + (size_t)(ib + r) * MPTS);
                    uint4 ka = Kr[t], kb = Kr[256 + t];
                    const __half2* a2 = (const __half2*)&ka;
                    const __half2* b2 = (const __half2*)&kb;
                    __half2 uh = su[r];
                    #pragma unroll
                    for (int q = 0; q < 4; q++){
                        Tsub[q]   = __hfma2(a2[q], uh, Tsub[q]);
                        Tsub[4+q] = __hfma2(b2[q], uh, Tsub[4+q]);
                    }
                }
                #pragma unroll
                for (int q = 0; q < 8; q++){
                    float2 fv = __half22float2(Tsub[q]);
                    Tacc[2*q]   += fv.x;
                    Tacc[2*q+1] += fv.y;
                }
            }
            // Pass B group 2: rows 8..11 predicated
            {
                __half2 Tsub[8];
                #pragma unroll
                for (int q = 0; q < 8; q++) Tsub[q] = hz;
                #pragma unroll
                for (int r = 8; r < CR3; r++){
                    if (r < ncr3){
                        const uint4* Kr = (const uint4*)(Kh + (size_t)(ib + r) * MPTS);
                        uint4 ka = Kr[t], kb = Kr[256 + t];
                        const __half2* a2 = (const __half2*)&ka;
                        const __half2* b2 = (const __half2*)&kb;
                        __half2 uh = su[r];
                        #pragma unroll
                        for (int q = 0; q < 4; q++){
                            Tsub[q]   = __hfma2(a2[q], uh, Tsub[q]);
                            Tsub[4+q] = __hfma2(b2[q], uh, Tsub[4+q]);
                        }
                    }
                }
                #pragma unroll
                for (int q = 0; q < 8; q++){
                    float2 fv = __half22float2(Tsub[q]);
                    Tacc[2*q]   += fv.x;
                    Tacc[2*q+1] += fv.y;
                }
            }
        }

        // store column partials (fp32, scaled by 2^24 via u')
        float4* Tp = (float4*)&g_T[slot][blk][0];
        Tp[2*t]       = make_float4(Tacc[0],  Tacc[1],  Tacc[2],  Tacc[3]);
        Tp[2*t+1]     = make_float4(Tacc[4],  Tacc[5],  Tacc[6],  Tacc[7]);
        Tp[512+2*t]   = make_float4(Tacc[8],  Tacc[9],  Tacc[10], Tacc[11]);
        Tp[512+2*t+1] = make_float4(Tacc[12], Tacc[13], Tacc[14], Tacc[15]);
        gbar(slot, tgt);

        // Column fix (coalesced): warp w sums partial rows [19w, 19w+19) at
        // column rstart+lane, then an 8-way SMEM combine. Pads are zero.
        {
            float s = 0.f;
            if (lane < ncols){
                int c = rstart + lane;
                #pragma unroll
                for (int p = 0; p < 19; p++)
                    s += __ldcg(&g_T[slot][19*warp + p][c]);
            }
            sB[warp][lane] = s;
            __syncthreads();
            if (t < 32 && lane < ncols){
                float T = 0.f;
                #pragma unroll
                for (int g = 0; g < 8; g++) T += sB[g][lane];
                g_v[slot][rstart + lane] = VSCALE / T;
            }
        }
        gbar(slot, tgt);
    }

    // ---- Phase 3: argmax of pi = u*K*v, survival, loss partials ----------
    {
        float vr[16];
        {
            float4 v0 = __ldcg((const float4*)(g_v[slot] + 8*t));
            float4 v1 = __ldcg((const float4*)(g_v[slot] + 8*t + 4));
            float4 v2 = __ldcg((const float4*)(g_v[slot] + 2048 + 8*t));
            float4 v3 = __ldcg((const float4*)(g_v[slot] + 2048 + 8*t + 4));
            vr[0]=v0.x; vr[1]=v0.y; vr[2]=v0.z;  vr[3]=v0.w;
            vr[4]=v1.x; vr[5]=v1.y; vr[6]=v1.z;  vr[7]=v1.w;
            vr[8]=v2.x; vr[9]=v2.y; vr[10]=v2.z; vr[11]=v2.w;
            vr[12]=v3.x; vr[13]=v3.y; vr[14]=v3.z; vr[15]=v3.w;
        }
        float cnt = 0.f, velsq = 0.f, bce = 0.f;   // thread 0 accumulates
        for (int i = rstart; i < rend; i++){
            const uint4* Kr = (const uint4*)(Kh + (size_t)i * MPTS);
            uint4 ka = Kr[t], kb = Kr[256 + t];
            float kf[16];
            cvt16(ka, kb, kf);
            float m = -1.f; int mi = 0;
            #pragma unroll
            for (int c = 0; c < 16; c++){
                float p = kf[c] * vr[c];
                int j = (c < 8) ? (8*t + c) : (2048 + 8*t + c - 8);
                if (p > m){ m = p; mi = j; }
            }
            #pragma unroll
            for (int o = 16; o; o >>= 1){
                float om = __shfl_xor_sync(0xffffffffu, m, o);
                int   oi = __shfl_xor_sync(0xffffffffu, mi, o);
                if (om > m || (om == m && oi < mi)){ m = om; mi = oi; }
            }
            if (lane == 0){ smx[warp] = m; smi[warp] = mi; }
            __syncthreads();
            if (t == 0){
                #pragma unroll
                for (int w = 1; w < 8; w++){
                    if (smx[w] > m || (smx[w] == m && smi[w] < mi)){
                        m = smx[w]; mi = smi[w];
                    }
                }
                float p = g_u[slot][i] * m;
                float a_i = al[i];
                float sp = fmaxf(a_i, 0.f) + log1pf(expf(-fabsf(a_i)));
                bce += sp;
                if (p > SURV_THRESH){
                    cnt += 1.f;
                    bce -= a_i;
                    #pragma unroll
                    for (int d = 0; d < 3; d++){
                        float vt = xg[3*mi + d] - x0[3*i + d];
                        float df = vp[3*i + d] - vt;
                        velsq = fmaf(df, df, velsq);
                    }
                }
            }
            __syncthreads();
        }
        if (t == 0){
            g_loss[b0 + slot][blk][0] = cnt;
            g_loss[b0 + slot][blk][1] = velsq;
            g_loss[b0 + slot][blk][2] = bce;
        }
    }
}

// ---------------------------------------------------------------------------
// Final reduction; also resets the barrier counters for the next replay
// (counters start at 0 from static init; every kernel_launch ends here).
__global__ void __launch_bounds__(NT) k_loss(float* __restrict__ out){
    int t = threadIdx.x;
    if (t < NSLOTS) g_bar[t].c = 0u;
    float cnt = 0.f, velsq = 0.f, bce = 0.f;
    for (int idx = t; idx < NBATCH * GB; idx += NT){
        int b = idx / GB, p = idx % GB;
        cnt   += g_loss[b][p][0];
        velsq += g_loss[b][p][1];
        bce   += g_loss[b][p][2];
    }
    cnt = warpSum(cnt); velsq = warpSum(velsq); bce = warpSum(bce);
    __shared__ float sc[8], sv[8], sb2[8];
    if ((t & 31) == 0){ sc[t>>5] = cnt; sv[t>>5] = velsq; sb2[t>>5] = bce; }
    __syncthreads();
    if (t == 0){
        float C = 0.f, V = 0.f, Bc = 0.f;
        #pragma unroll
        for (int w = 0; w < 8; w++){ C += sc[w]; V += sv[w]; Bc += sb2[w]; }
        float denom = fmaxf(C, 1.f);
        out[0] = V / denom + Bc / (float)(NBATCH * MPTS);
    }
}

// ---------------------------------------------------------------------------
extern "C" void kernel_launch(void* const* d_in, const int* in_sizes, int n_in,
                              void* d_out, int out_size){
    const float* x0 = (const float*)d_in[0];   // (B, M, 3)
    const float* xg = (const float*)d_in[1];   // (B, K, 3)
    const float* vp = (const float*)d_in[2];   // (B, M, 3)
    const float* al = (const float*)d_in[3];   // (B, M, 1)
    (void)in_sizes; (void)n_in; (void)out_size;

    for (int l = 0; l < NBATCH / NSLOTS; l++){
        int b0 = l * NSLOTS;
        k_persist<<<GRID, NT>>>(x0 + (size_t)b0 * MPTS * 3,
                                xg + (size_t)b0 * MPTS * 3,
                                vp + (size_t)b0 * MPTS * 3,
                                al + (size_t)b0 * MPTS,
                                b0, (unsigned)(l * NBARS * GB));
    }
    k_loss<<<1, NT>>>((float*)d_out);
}

// round 15
// speedup vs baseline: 1.4289x; 1.0373x over previous
#include <cuda_runtime.h>
#include <cuda_fp16.h>
#include <cstdint>
#include <math.h>

// Problem constants (fixed by the reference setup_inputs)
#define MPTS   4096
#define NBATCH 4
#define NITERS 50
#define NSLOTS 2            // batches concurrent per launch (L2-resident: 64MB)
#define GB     148          // blocks per slot -> 296 total = 2/SM on 148 SMs
#define GRID   (NSLOTS*GB)
#define NT     512          // 512 thr/block, 2 blocks/SM -> 32 warps/SM
#define NW     16           // warps per block
#define CR     8            // rows per full chunk
#define CR3    12           // max rows in merged third chunk (11 or 12)
#define TPAD   160          // partial rows padded to 16*10 (pads stay zero)
#define INV_N  (1.0f/4096.0f)
#define USCALE 16777216.0f  // 2^24 : u scaled into half-friendly range
#define VSCALE 4096.0f      // INV_N * 2^24 : folded into colfix division
#define SURV_THRESH 1e-5f
#define NBARS  (2 + 2*NITERS)   // grid barriers per slot per launch

// Scratch (device globals; allocation-free per harness rules).
__device__ __half g_K16[NSLOTS][(size_t)MPTS * MPTS];   // 2 x 32 MB, L2-resident
__device__ float  g_u[NSLOTS][MPTS];
__device__ float  g_v[NSLOTS][MPTS];
__device__ float  g_T[NSLOTS][TPAD][MPTS];              // partials; rows 148..159 = 0
__device__ float  g_cmax[NSLOTS][GB];
__device__ float  g_loss[NBATCH][GB][3];                // cnt, velsq, bce
struct Bar { unsigned c; unsigned pad[31]; };           // 128B separation
__device__ Bar g_bar[NSLOTS];

__device__ __forceinline__ float warpMax(float v){
    #pragma unroll
    for (int o = 16; o; o >>= 1) v = fmaxf(v, __shfl_xor_sync(0xffffffffu, v, o));
    return v;
}
__device__ __forceinline__ float warpSum(float v){
    #pragma unroll
    for (int o = 16; o; o >>= 1) v += __shfl_xor_sync(0xffffffffu, v, o);
    return v;
}
__device__ __forceinline__ float ex2(float x){
    float r; asm("ex2.approx.f32 %0, %1;" : "=f"(r) : "f"(x)); return r;
}

// Software grid barrier among the GB blocks of one slot.
__device__ __forceinline__ void gbar(int slot, unsigned &tgt){
    __syncthreads();
    if (threadIdx.x == 0){
        __threadfence();
        atomicAdd(&g_bar[slot].c, 1u);
        while (*((volatile unsigned*)&g_bar[slot].c) < tgt) __nanosleep(32);
    }
    __syncthreads();
    tgt += GB;
}

// ---------------------------------------------------------------------------
// Persistent kernel: 2 batch slots of 148 blocks each (one block of each slot
// per SM). NT=512: each thread owns 8 columns (one uint4 per K row), halving
// per-thread registers so 2 blocks x 16 warps co-reside -> 32 warps/SM for
// latency hiding (the R7-R14 plateau was occupancy-bound at 16 warps/SM).
// Phases per slot: cmax -> exp(K16) -> 50x(rowpass{8,8,11|12} -> colfix) ->
// argmax/loss partials.
// ---------------------------------------------------------------------------
__global__ void __launch_bounds__(NT, 2) k_persist(
        const float* __restrict__ x0p, const float* __restrict__ xgp,
        const float* __restrict__ vpp, const float* __restrict__ alp,
        int b0, unsigned base)
{
    int t = threadIdx.x, warp = t >> 5, lane = t & 31;
    int slot = (blockIdx.x >= GB) ? 1 : 0;
    int blk  = blockIdx.x - slot * GB;
    const float* x0 = x0p + (size_t)slot * MPTS * 3;
    const float* xg = xgp + (size_t)slot * MPTS * 3;
    const float* vp = vpp + (size_t)slot * MPTS * 3;
    const float* al = alp + (size_t)slot * MPTS;
    __half* Kh = g_K16[slot];

    __shared__ float   red[CR3][NT];        // row-sum partials (24 KB)
    __shared__ __half2 su[CR3];             // scaled u' per chunk row
    __shared__ float   sr16[NW];
    __shared__ float   s_scalar;
    __shared__ float   smx[NW];
    __shared__ int     smi[NW];
    __shared__ float   sB[NW][33];          // colfix transpose buffer

    unsigned tgt = base + GB;
    int rstart = (blk * MPTS) / GB;
    int rend   = ((blk + 1) * MPTS) / GB;   // 27 or 28 rows
    int ncols  = rend - rstart;
    int ncr3   = ncols - 16;                // 11 or 12 rows in chunk 3

    // Thread t owns columns j = 8t..8t+7.
    {
        float gx[8], gy[8], gz[8];
        {
            const float* bg = xg + 24 * t;
            #pragma unroll
            for (int c = 0; c < 8; c++){
                gx[c] = bg[3*c]; gy[c] = bg[3*c+1]; gz[c] = bg[3*c+2];
            }
        }

        // ---- Phase 0: block-local cost max -------------------------------
        float mx = 0.f;
        for (int i = rstart; i < rend; i++){
            float ax = x0[3*i], ay = x0[3*i+1], az = x0[3*i+2];
            #pragma unroll
            for (int c = 0; c < 8; c++){
                float dx = ax-gx[c], dy = ay-gy[c], dz = az-gz[c];
                mx = fmaxf(mx, dx*dx + dy*dy + dz*dz);
            }
        }
        mx = warpMax(mx);
        if (lane == 0) sr16[warp] = mx;
        __syncthreads();
        if (t == 0){
            float m = sr16[0];
            #pragma unroll
            for (int w = 1; w < NW; w++) m = fmaxf(m, sr16[w]);
            g_cmax[slot][blk] = m;
        }
        gbar(slot, tgt);

        // ---- Phase 1: global max -> scale; K16 = 2^4*exp(-C/(reg*cmax)) --
        float mc = (t < GB) ? __ldcg(&g_cmax[slot][t]) : 0.f;
        mc = warpMax(mc);
        if (lane == 0) sr16[warp] = mc;
        __syncthreads();
        if (t == 0){
            float m = sr16[0];
            #pragma unroll
            for (int w = 1; w < NW; w++) m = fmaxf(m, sr16[w]);
            s_scalar = -1.44269504088896340736f / (0.1f * m);
        }
        __syncthreads();
        float scale = s_scalar;
        for (int i = rstart; i < rend; i++){
            float ax = x0[3*i], ay = x0[3*i+1], az = x0[3*i+2];
            __half2 hk[4];
            #pragma unroll
            for (int c = 0; c < 8; c += 2){
                float dx = ax-gx[c],   dy = ay-gy[c],   dz = az-gz[c];
                float e0 = ex2(fmaf(dx*dx + dy*dy + dz*dz, scale, 4.0f));
                dx = ax-gx[c+1]; dy = ay-gy[c+1]; dz = az-gz[c+1];
                float e1 = ex2(fmaf(dx*dx + dy*dy + dz*dz, scale, 4.0f));
                hk[c/2] = __floats2half2_rn(e0, e1);
            }
            ((uint4*)(Kh + (size_t)i * MPTS))[t] = *(uint4*)&hk[0];
        }
        if (blk == 0){
            #pragma unroll
            for (int q = 0; q < 8; q++) g_v[slot][t + 512*q] = 1.0f;
        }
    }
    gbar(slot, tgt);

    // ---- Phase 2: 50 Sinkhorn iterations (HFMA2 inner loops) -------------
    for (int it = 0; it < NITERS; it++){
        // load v (cross-block -> L2) and convert to half2 lanes
        __half2 vh[4];
        {
            float4 v0 = __ldcg((const float4*)(g_v[slot] + 8*t));
            float4 v1 = __ldcg((const float4*)(g_v[slot] + 8*t + 4));
            vh[0] = __floats2half2_rn(v0.x, v0.y); vh[1] = __floats2half2_rn(v0.z, v0.w);
            vh[2] = __floats2half2_rn(v1.x, v1.y); vh[3] = __floats2half2_rn(v1.z, v1.w);
        }
        float Tacc[8];
        #pragma unroll
        for (int c = 0; c < 8; c++) Tacc[c] = 0.f;

        const __half2 hz = __floats2half2_rn(0.f, 0.f);

        // ---- Chunks 0 and 1: 8 unconditional rows each
        #pragma unroll 1
        for (int f = 0; f < 2; f++){
            int ib = rstart + f * CR;
            // Pass A: 8 independent row sums, no predicates, no syncs
            #pragma unroll
            for (int r = 0; r < CR; r++){
                uint4 ka = ((const uint4*)(Kh + (size_t)(ib + r) * MPTS))[t];
                const __half2* a2 = (const __half2*)&ka;
                __half2 acc = hz;
                #pragma unroll
                for (int q = 0; q < 4; q++) acc = __hfma2(a2[q], vh[q], acc);
                float2 fv = __half22float2(acc);
                red[r][t] = fv.x + fv.y;
            }
            __syncthreads();
            // Block reduce: warp w (w<8) reduces row w
            if (warp < CR){
                float S = 0.f;
                #pragma unroll
                for (int q = 0; q < NW; q++) S += red[warp][lane + 32*q];
                S = warpSum(S);
                if (lane == 0){
                    float u = INV_N / S;
                    g_u[slot][ib + warp] = u;
                    su[warp] = __float2half2_rn(u * USCALE);
                }
            }
            __syncthreads();
            // Pass B: re-read same rows (L1-hot); chunk subtotal in half2
            {
                __half2 Tsub[4];
                #pragma unroll
                for (int q = 0; q < 4; q++) Tsub[q] = hz;
                #pragma unroll
                for (int r = 0; r < CR; r++){
                    uint4 ka = ((const uint4*)(Kh + (size_t)(ib + r) * MPTS))[t];
                    const __half2* a2 = (const __half2*)&ka;
                    __half2 uh = su[r];
                    #pragma unroll
                    for (int q = 0; q < 4; q++) Tsub[q] = __hfma2(a2[q], uh, Tsub[q]);
                }
                #pragma unroll
                for (int q = 0; q < 4; q++){
                    float2 fv = __half22float2(Tsub[q]);
                    Tacc[2*q]   += fv.x;
                    Tacc[2*q+1] += fv.y;
                }
            }
        }

        // ---- Chunk 2: 11|12 rows (8 unconditional + 3|4 predicated) ------
        {
            int ib = rstart + 16;
            #pragma unroll
            for (int r = 0; r < 8; r++){
                uint4 ka = ((const uint4*)(Kh + (size_t)(ib + r) * MPTS))[t];
                const __half2* a2 = (const __half2*)&ka;
                __half2 acc = hz;
                #pragma unroll
                for (int q = 0; q < 4; q++) acc = __hfma2(a2[q], vh[q], acc);
                float2 fv = __half22float2(acc);
                red[r][t] = fv.x + fv.y;
            }
            #pragma unroll
            for (int r = 8; r < CR3; r++){
                if (r < ncr3){
                    uint4 ka = ((const uint4*)(Kh + (size_t)(ib + r) * MPTS))[t];
                    const __half2* a2 = (const __half2*)&ka;
                    __half2 acc = hz;
                    #pragma unroll
                    for (int q = 0; q < 4; q++) acc = __hfma2(a2[q], vh[q], acc);
                    float2 fv = __half22float2(acc);
                    red[r][t] = fv.x + fv.y;
                }
            }
            __syncthreads();
            // Block reduce: warp w (w < ncr3 <= 12 < NW) reduces row w
            if (warp < ncr3){
                float S = 0.f;
                #pragma unroll
                for (int q = 0; q < NW; q++) S += red[warp][lane + 32*q];
                S = warpSum(S);
                if (lane == 0){
                    float u = INV_N / S;
                    g_u[slot][ib + warp] = u;
                    su[warp] = __float2half2_rn(u * USCALE);
                }
            }
            __syncthreads();
            // Pass B group 1: rows 0..7
            {
                __half2 Tsub[4];
                #pragma unroll
                for (int q = 0; q < 4; q++) Tsub[q] = hz;
                #pragma unroll
                for (int r = 0; r < 8; r++){
                    uint4 ka = ((const uint4*)(Kh + (size_t)(ib + r) * MPTS))[t];
                    const __half2* a2 = (const __half2*)&ka;
                    __half2 uh = su[r];
                    #pragma unroll
                    for (int q = 0; q < 4; q++) Tsub[q] = __hfma2(a2[q], uh, Tsub[q]);
                }
                #pragma unroll
                for (int q = 0; q < 4; q++){
                    float2 fv = __half22float2(Tsub[q]);
                    Tacc[2*q]   += fv.x;
                    Tacc[2*q+1] += fv.y;
                }
            }
            // Pass B group 2: rows 8..11 predicated
            {
                __half2 Tsub[4];
                #pragma unroll
                for (int q = 0; q < 4; q++) Tsub[q] = hz;
                #pragma unroll
                for (int r = 8; r < CR3; r++){
                    if (r < ncr3){
                        uint4 ka = ((const uint4*)(Kh + (size_t)(ib + r) * MPTS))[t];
                        const __half2* a2 = (const __half2*)&ka;
                        __half2 uh = su[r];
                        #pragma unroll
                        for (int q = 0; q < 4; q++) Tsub[q] = __hfma2(a2[q], uh, Tsub[q]);
                    }
                }
                #pragma unroll
                for (int q = 0; q < 4; q++){
                    float2 fv = __half22float2(Tsub[q]);
                    Tacc[2*q]   += fv.x;
                    Tacc[2*q+1] += fv.y;
                }
            }
        }

        // store column partials (fp32, scaled by 2^24 via u')
        float4* Tp = (float4*)&g_T[slot][blk][0];
        Tp[2*t]   = make_float4(Tacc[0], Tacc[1], Tacc[2], Tacc[3]);
        Tp[2*t+1] = make_float4(Tacc[4], Tacc[5], Tacc[6], Tacc[7]);
        gbar(slot, tgt);

        // Column fix (coalesced): warp w sums partial rows [10w, 10w+10) at
        // column rstart+lane, then a 16-way SMEM combine. Pads are zero.
        {
            float s = 0.f;
            if (lane < ncols){
                int c = rstart + lane;
                #pragma unroll
                for (int p = 0; p < 10; p++)
                    s += __ldcg(&g_T[slot][10*warp + p][c]);
            }
            sB[warp][lane] = s;
            __syncthreads();
            if (t < 32 && lane < ncols){
                float T = 0.f;
                #pragma unroll
                for (int g = 0; g < NW; g++) T += sB[g][lane];
                g_v[slot][rstart + lane] = VSCALE / T;
            }
        }
        gbar(slot, tgt);
    }

    // ---- Phase 3: argmax of pi = u*K*v, survival, loss partials ----------
    {
        float vr[8];
        {
            float4 v0 = __ldcg((const float4*)(g_v[slot] + 8*t));
            float4 v1 = __ldcg((const float4*)(g_v[slot] + 8*t + 4));
            vr[0]=v0.x; vr[1]=v0.y; vr[2]=v0.z; vr[3]=v0.w;
            vr[4]=v1.x; vr[5]=v1.y; vr[6]=v1.z; vr[7]=v1.w;
        }
        float cnt = 0.f, velsq = 0.f, bce = 0.f;   // thread 0 accumulates
        for (int i = rstart; i < rend; i++){
            uint4 ka = ((const uint4*)(Kh + (size_t)i * MPTS))[t];
            const __half2* a2 = (const __half2*)&ka;
            float m = -1.f; int mi = 0;
            #pragma unroll
            for (int q = 0; q < 4; q++){
                float2 f = __half22float2(a2[q]);
                float p0 = f.x * vr[2*q], p1 = f.y * vr[2*q+1];
                if (p0 > m){ m = p0; mi = 8*t + 2*q; }
                if (p1 > m){ m = p1; mi = 8*t + 2*q + 1; }
            }
            #pragma unroll
            for (int o = 16; o; o >>= 1){
                float om = __shfl_xor_sync(0xffffffffu, m, o);
                int   oi = __shfl_xor_sync(0xffffffffu, mi, o);
                if (om > m || (om == m && oi < mi)){ m = om; mi = oi; }
            }
            if (lane == 0){ smx[warp] = m; smi[warp] = mi; }
            __syncthreads();
            if (t == 0){
                #pragma unroll
                for (int w = 1; w < NW; w++){
                    if (smx[w] > m || (smx[w] == m && smi[w] < mi)){
                        m = smx[w]; mi = smi[w];
                    }
                }
                float p = g_u[slot][i] * m;
                float a_i = al[i];
                float sp = fmaxf(a_i, 0.f) + log1pf(expf(-fabsf(a_i)));
                bce += sp;
                if (p > SURV_THRESH){
                    cnt += 1.f;
                    bce -= a_i;
                    #pragma unroll
                    for (int d = 0; d < 3; d++){
                        float vt = xg[3*mi + d] - x0[3*i + d];
                        float df = vp[3*i + d] - vt;
                        velsq = fmaf(df, df, velsq);
                    }
                }
            }
            __syncthreads();
        }
        if (t == 0){
            g_loss[b0 + slot][blk][0] = cnt;
            g_loss[b0 + slot][blk][1] = velsq;
            g_loss[b0 + slot][blk][2] = bce;
        }
    }
}

// ---------------------------------------------------------------------------
// Final reduction; also resets the barrier counters for the next replay
// (counters start at 0 from static init; every kernel_launch ends here).
__global__ void __launch_bounds__(256) k_loss(float* __restrict__ out){
    int t = threadIdx.x;
    if (t < NSLOTS) g_bar[t].c = 0u;
    float cnt = 0.f, velsq = 0.f, bce = 0.f;
    for (int idx = t; idx < NBATCH * GB; idx += 256){
        int b = idx / GB, p = idx % GB;
        cnt   += g_loss[b][p][0];
        velsq += g_loss[b][p][1];
        bce   += g_loss[b][p][2];
    }
    cnt = warpSum(cnt); velsq = warpSum(velsq); bce = warpSum(bce);
    __shared__ float sc[8], sv[8], sb2[8];
    if ((t & 31) == 0){ sc[t>>5] = cnt; sv[t>>5] = velsq; sb2[t>>5] = bce; }
    __syncthreads();
    if (t == 0){
        float C = 0.f, V = 0.f, Bc = 0.f;
        #pragma unroll
        for (int w = 0; w < 8; w++){ C += sc[w]; V += sv[w]; Bc += sb2[w]; }
        float denom = fmaxf(C, 1.f);
        out[0] = V / denom + Bc / (float)(NBATCH * MPTS);
    }
}

// ---------------------------------------------------------------------------
extern "C" void kernel_launch(void* const* d_in, const int* in_sizes, int n_in,
                              void* d_out, int out_size){
    const float* x0 = (const float*)d_in[0];   // (B, M, 3)
    const float* xg = (const float*)d_in[1];   // (B, K, 3)
    const float* vp = (const float*)d_in[2];   // (B, M, 3)
    const float* al = (const float*)d_in[3];   // (B, M, 1)
    (void)in_sizes; (void)n_in; (void)out_size;

    for (int l = 0; l < NBATCH / NSLOTS; l++){
        int b0 = l * NSLOTS;
        k_persist<<<GRID, NT>>>(x0 + (size_t)b0 * MPTS * 3,
                                xg + (size_t)b0 * MPTS * 3,
                                vp + (size_t)b0 * MPTS * 3,
                                al + (size_t)b0 * MPTS,
                                b0, (unsigned)(l * NBARS * GB));
    }
    k_loss<<<1, 256>>>((float*)d_out);
}